// round 4
// baseline (speedup 1.0000x reference)
#include <cuda_runtime.h>

#define D_MODEL 512
#define NHEAD   8
#define HD      64
#define BATCH   2
#define SEQ     2048
#define SCALE   0.125f   // 1/sqrt(64)

// ---------------- scratch (no allocations allowed) ----------------
__device__ float g_Q[BATCH*NHEAD*SEQ*HD];   // pre-scaled by SCALE
__device__ float g_K[BATCH*NHEAD*SEQ*HD];
__device__ float g_V[BATCH*NHEAD*SEQ*HD];
__device__ float g_cp[BATCH*NHEAD*SEQ];     // coord projection per (b,h,n)

// ---------------- coord projection: cp[b,h,n] = coords[b,n,:]·rw[h,:] ----
__global__ void coord_proj_kernel(const float* __restrict__ coords,
                                  const float* __restrict__ rw) {
    int idx = blockIdx.x * blockDim.x + threadIdx.x;    // (b*8+h)*2048+n
    if (idx >= BATCH*NHEAD*SEQ) return;
    int n = idx & (SEQ - 1);
    int h = (idx >> 11) & 7;
    int b = idx >> 14;
    const float* c = coords + (b*SEQ + n)*3;
    const float* w = rw + h*3;
    g_cp[idx] = c[0]*w[0] + c[1]*w[1] + c[2]*w[2];
}

// ---------------- QKV GEMM: qkv[m,o] = x[m,:]·w[o,:] + b[o] -------------
// 64x64 tile, K-chunk 32, 256 threads, 4x4 microtile.
// Output scattered directly into per-head Q/K/V layout; Q pre-scaled.
#define GBK     32
#define ASTRIDE 36      // 32 + 4 pad; row*36 words -> 144B, 16B aligned

__global__ __launch_bounds__(256)
void qkv_gemm_kernel(const float* __restrict__ x,
                     const float* __restrict__ w,
                     const float* __restrict__ bias) {
    __shared__ float As[64*ASTRIDE];   // [m][k] natural
    __shared__ float Bs[64*ASTRIDE];   // [o][k] natural
    const int m0 = blockIdx.y * 64;
    const int o0 = blockIdx.x * 64;
    const int tid = threadIdx.x;
    const int ty = tid >> 4, tx = tid & 15;

    float acc[4][4] = {};

    for (int k0 = 0; k0 < D_MODEL; k0 += GBK) {
        #pragma unroll
        for (int t = 0; t < 2; t++) {
            int slot = tid + t*256;                 // 0..511
            int row = slot >> 3, c4 = slot & 7;     // 64 rows x 8 float4
            *(float4*)&As[row*ASTRIDE + c4*4] =
                *(const float4*)&x[(long)(m0+row)*D_MODEL + k0 + c4*4];
            *(float4*)&Bs[row*ASTRIDE + c4*4] =
                *(const float4*)&w[(long)(o0+row)*D_MODEL + k0 + c4*4];
        }
        __syncthreads();
        #pragma unroll
        for (int kk = 0; kk < GBK; kk++) {
            float a[4], bb[4];
            #pragma unroll
            for (int i = 0; i < 4; i++) a[i]  = As[(ty*4+i)*ASTRIDE + kk];   // broadcast
            #pragma unroll
            for (int j = 0; j < 4; j++) bb[j] = Bs[(tx+16*j)*ASTRIDE + kk];  // 2-way max
            #pragma unroll
            for (int i = 0; i < 4; i++)
                #pragma unroll
                for (int j = 0; j < 4; j++)
                    acc[i][j] += a[i] * bb[j];
        }
        __syncthreads();
    }

    const int which = o0 >> 9;            // 0=q 1=k 2=v (tiles never straddle)
    const int h = (o0 >> 6) & 7;
    float* dstbase = (which == 0) ? g_Q : (which == 1 ? g_K : g_V);
    const float sc = (which == 0) ? SCALE : 1.0f;
    #pragma unroll
    for (int i = 0; i < 4; i++) {
        int m = m0 + ty*4 + i;
        int b = m >> 11, n = m & 2047;
        float* dst = dstbase + ((long)(b*NHEAD + h)*SEQ + n)*HD;
        #pragma unroll
        for (int j = 0; j < 4; j++) {
            int dd = tx + 16*j;
            dst[dd] = (acc[i][j] + bias[o0 + dd]) * sc;
        }
    }
}

// ---------------- flash attention, fp32, online softmax ------------------
// Block = (b, h, 64-query tile). 256 threads; 4 query rows x 4 key cols per
// thread (keys strided tx+16j to keep stride-68 rows at 2-way conflicts).
// score = q·k (Q pre-scaled) + mask[q,k] - cp[k]   (cp[q] row-shift dropped)
#define PADS 68

__global__ __launch_bounds__(256)
void flash_kernel(const float* __restrict__ mask, float* __restrict__ out) {
    extern __shared__ float sm[];
    float* Qs   = sm;                    // 64*68
    float* Ks   = Qs + 64*PADS;          // K tile, reused for P
    float* Vs   = Ks + 64*PADS;
    float* red  = Vs + 64*PADS;          // 64*16 reduction buffer
    float* sm_m = red + 64*16;           // 64 row max
    float* sm_l = sm_m + 64;             // 64 row sum
    float* sm_a = sm_l + 64;             // 64 rescale alpha
    float* cpk  = sm_a + 64;             // 64 key coord-proj

    const int b = blockIdx.z, h = blockIdx.y;
    const int q0 = blockIdx.x * 64;
    const int tid = threadIdx.x;
    const int ty = tid >> 4, tx = tid & 15;

    const long base = (long)(b*NHEAD + h) * SEQ;
    const float* Qg  = g_Q + (base + q0) * HD;
    const float* Kg  = g_K + base * HD;
    const float* Vg  = g_V + base * HD;
    const float* cpb = g_cp + base;

    #pragma unroll
    for (int t = 0; t < 4; t++) {
        int slot = tid + t*256;
        int r = slot >> 4, c4 = slot & 15;
        *(float4*)&Qs[r*PADS + c4*4] = *(const float4*)&Qg[r*HD + c4*4];
    }
    if (tid < 64) { sm_m[tid] = -1e30f; sm_l[tid] = 0.f; }
    float o[4][4] = {};
    __syncthreads();

    for (int kt = 0; kt < SEQ/64; kt++) {
        const int k0 = kt * 64;
        #pragma unroll
        for (int t = 0; t < 4; t++) {
            int slot = tid + t*256;
            int r = slot >> 4, c4 = slot & 15;
            *(float4*)&Ks[r*PADS + c4*4] = *(const float4*)&Kg[(long)(k0+r)*HD + c4*4];
            *(float4*)&Vs[r*PADS + c4*4] = *(const float4*)&Vg[(long)(k0+r)*HD + c4*4];
        }
        if (tid < 64) cpk[tid] = cpb[k0 + tid];
        __syncthreads();

        // ---- S = Q·K^T (Q pre-scaled) ----
        float s[4][4] = {};
        #pragma unroll
        for (int d = 0; d < HD; d += 4) {
            float4 qv[4], kv[4];
            #pragma unroll
            for (int i = 0; i < 4; i++) qv[i] = *(float4*)&Qs[(ty*4+i)*PADS + d];
            #pragma unroll
            for (int j = 0; j < 4; j++) kv[j] = *(float4*)&Ks[(tx+16*j)*PADS + d];
            #pragma unroll
            for (int i = 0; i < 4; i++)
                #pragma unroll
                for (int j = 0; j < 4; j++)
                    s[i][j] += qv[i].x*kv[j].x + qv[i].y*kv[j].y
                             + qv[i].z*kv[j].z + qv[i].w*kv[j].w;
        }

        // ---- bias + per-thread row max ----
        #pragma unroll
        for (int i = 0; i < 4; i++) {
            int r = ty*4 + i;
            const float* mrow = mask + (long)(q0 + r)*SEQ + k0;
            float rm = -1e30f;
            #pragma unroll
            for (int j = 0; j < 4; j++) {
                int c = tx + 16*j;
                s[i][j] += __ldg(mrow + c) - cpk[c];
                rm = fmaxf(rm, s[i][j]);
            }
            red[r*16 + tx] = rm;
        }
        __syncthreads();

        // ---- row stats update (1 thread per row) ----
        if (tid < 64) {
            float mt = red[tid*16];
            #pragma unroll
            for (int t2 = 1; t2 < 16; t2++) mt = fmaxf(mt, red[tid*16 + t2]);
            float mold = sm_m[tid];
            float mnew = fmaxf(mold, mt);
            float alpha = __expf(mold - mnew);
            sm_m[tid] = mnew;
            sm_a[tid] = alpha;
            sm_l[tid] *= alpha;
        }
        __syncthreads();

        // ---- P = exp(S - m), rescale O, partial row sums ----
        #pragma unroll
        for (int i = 0; i < 4; i++) {
            int r = ty*4 + i;
            float mrow = sm_m[r];
            float a = sm_a[r];
            float ls = 0.f;
            #pragma unroll
            for (int j = 0; j < 4; j++) {
                float p = __expf(s[i][j] - mrow);
                Ks[r*PADS + tx + 16*j] = p;       // P overwrites K tile
                ls += p;
            }
            o[i][0] *= a; o[i][1] *= a; o[i][2] *= a; o[i][3] *= a;
            red[r*16 + tx] = ls;
        }
        __syncthreads();
        if (tid < 64) {
            float ssum = 0.f;
            #pragma unroll
            for (int t2 = 0; t2 < 16; t2++) ssum += red[tid*16 + t2];
            sm_l[tid] += ssum;
        }

        // ---- O += P·V ----
        #pragma unroll 8
        for (int kk = 0; kk < 64; kk++) {
            float4 v4 = *(float4*)&Vs[kk*PADS + tx*4];
            #pragma unroll
            for (int i = 0; i < 4; i++) {
                float p = Ks[(ty*4+i)*PADS + kk];
                o[i][0] += p*v4.x; o[i][1] += p*v4.y;
                o[i][2] += p*v4.z; o[i][3] += p*v4.w;
            }
        }
        __syncthreads();   // protects Ks/Vs reuse + sm_l final value
    }

    // ---- epilogue: normalize, write [B,N,D] with head offset ----
    #pragma unroll
    for (int i = 0; i < 4; i++) {
        int r = ty*4 + i;
        float inv = 1.f / sm_l[r];
        float4 res;
        res.x = o[i][0]*inv; res.y = o[i][1]*inv;
        res.z = o[i][2]*inv; res.w = o[i][3]*inv;
        *(float4*)&out[(long)(b*SEQ + q0 + r)*D_MODEL + h*HD + tx*4] = res;
    }
}

// ---------------- launch ----------------
#define FLASH_SMEM ((3*64*PADS + 64*16 + 4*64) * (int)sizeof(float))  // 57344

extern "C" void kernel_launch(void* const* d_in, const int* in_sizes, int n_in,
                              void* d_out, int out_size) {
    const float* x      = (const float*)d_in[0];
    const float* coords = (const float*)d_in[1];
    const float* mask   = (const float*)d_in[2];
    const float* qkv_w  = (const float*)d_in[3];
    const float* qkv_b  = (const float*)d_in[4];
    const float* rw     = (const float*)d_in[5];
    float* out = (float*)d_out;

    coord_proj_kernel<<<(BATCH*NHEAD*SEQ + 255)/256, 256>>>(coords, rw);

    dim3 ggrid(3*D_MODEL/64, BATCH*SEQ/64);
    qkv_gemm_kernel<<<ggrid, 256>>>(x, qkv_w, qkv_b);

    cudaFuncSetAttribute(flash_kernel,
                         cudaFuncAttributeMaxDynamicSharedMemorySize, FLASH_SMEM);
    dim3 fgrid(SEQ/64, NHEAD, BATCH);
    flash_kernel<<<fgrid, 256, FLASH_SMEM>>>(mask, out);
}

// round 5
// speedup vs baseline: 3.1859x; 3.1859x over previous
#include <cuda_runtime.h>
#include <cuda_fp16.h>

#define D_MODEL 512
#define NHEAD   8
#define HD      64
#define BATCH   2
#define SEQ     2048
#define LOG2E   1.4426950408889634f
#define QSCALE  (0.125f * LOG2E)     // 1/sqrt(64) * log2(e), folded into Q

// ---------------- scratch ----------------
__device__ float g_Q[BATCH*NHEAD*SEQ*HD];   // pre-scaled by QSCALE
__device__ float g_K[BATCH*NHEAD*SEQ*HD];
__device__ float g_V[BATCH*NHEAD*SEQ*HD];
__device__ float g_cp[BATCH*NHEAD*SEQ];     // coord proj, pre-scaled by LOG2E

// ---------------- helpers ----------------
static __device__ __forceinline__ unsigned f2tf(float x) {
    unsigned r; asm("cvt.rna.tf32.f32 %0, %1;" : "=r"(r) : "f"(x)); return r;
}
static __device__ __forceinline__ void mma_tf32(float d[4], const unsigned a[4],
                                                unsigned b0, unsigned b1) {
    asm volatile("mma.sync.aligned.m16n8k8.row.col.f32.tf32.tf32.f32 "
                 "{%0,%1,%2,%3},{%4,%5,%6,%7},{%8,%9},{%0,%1,%2,%3};"
                 : "+f"(d[0]), "+f"(d[1]), "+f"(d[2]), "+f"(d[3])
                 : "r"(a[0]), "r"(a[1]), "r"(a[2]), "r"(a[3]), "r"(b0), "r"(b1));
}
static __device__ __forceinline__ void mma_f16(float d[4], const unsigned a[4],
                                               unsigned b0, unsigned b1) {
    asm volatile("mma.sync.aligned.m16n8k16.row.col.f32.f16.f16.f32 "
                 "{%0,%1,%2,%3},{%4,%5,%6,%7},{%8,%9},{%0,%1,%2,%3};"
                 : "+f"(d[0]), "+f"(d[1]), "+f"(d[2]), "+f"(d[3])
                 : "r"(a[0]), "r"(a[1]), "r"(a[2]), "r"(a[3]), "r"(b0), "r"(b1));
}
static __device__ __forceinline__ unsigned packh2(float a, float b) {
    __half2 h = __floats2half2_rn(a, b);
    return *reinterpret_cast<unsigned*>(&h);
}
static __device__ __forceinline__ unsigned smem_u32(const void* p) {
    return (unsigned)__cvta_generic_to_shared(p);
}

// ---------------- coord projection (×LOG2E) ----------------
__global__ void coord_proj_kernel(const float* __restrict__ coords,
                                  const float* __restrict__ rw) {
    int idx = blockIdx.x * blockDim.x + threadIdx.x;
    if (idx >= BATCH*NHEAD*SEQ) return;
    int n = idx & (SEQ - 1);
    int h = (idx >> 11) & 7;
    int b = idx >> 14;
    const float* c = coords + (b*SEQ + n)*3;
    const float* w = rw + h*3;
    g_cp[idx] = (c[0]*w[0] + c[1]*w[1] + c[2]*w[2]) * LOG2E;
}

// ---------------- QKV GEMM (tf32 mma) ----------------
// 64x64 tile, K-chunk 32, 128 threads (4 warps x 16 rows).
#define GS 36
__global__ __launch_bounds__(128)
void qkv_gemm_kernel(const float* __restrict__ x,
                     const float* __restrict__ w,
                     const float* __restrict__ bias) {
    __shared__ unsigned Xs[64*GS];
    __shared__ unsigned Ws[64*GS];
    const int m0 = blockIdx.y * 64, o0 = blockIdx.x * 64;
    const int tid = threadIdx.x, lane = tid & 31, warp = tid >> 5;
    const int g = lane >> 2, t = lane & 3, wm = warp * 16;

    float c[8][4] = {};

    for (int k0 = 0; k0 < D_MODEL; k0 += 32) {
        #pragma unroll
        for (int s = 0; s < 4; s++) {
            int slot = tid + s*128;               // 0..511
            int row = slot >> 3, c4 = slot & 7;   // 64 rows x 8 float4
            float4 xv = *(const float4*)&x[(size_t)(m0+row)*D_MODEL + k0 + c4*4];
            float4 wv = *(const float4*)&w[(size_t)(o0+row)*D_MODEL + k0 + c4*4];
            uint4 xt = { f2tf(xv.x), f2tf(xv.y), f2tf(xv.z), f2tf(xv.w) };
            uint4 wt = { f2tf(wv.x), f2tf(wv.y), f2tf(wv.z), f2tf(wv.w) };
            *(uint4*)&Xs[row*GS + c4*4] = xt;
            *(uint4*)&Ws[row*GS + c4*4] = wt;
        }
        __syncthreads();
        #pragma unroll
        for (int kk = 0; kk < 4; kk++) {
            unsigned a[4];
            int ab = (wm + g)*GS + kk*8 + t;
            a[0] = Xs[ab];        a[1] = Xs[ab + 8*GS];
            a[2] = Xs[ab + 4];    a[3] = Xs[ab + 8*GS + 4];
            #pragma unroll
            for (int j = 0; j < 8; j++) {
                int bb = (j*8 + g)*GS + kk*8 + t;
                mma_tf32(c[j], a, Ws[bb], Ws[bb + 4]);
            }
        }
        __syncthreads();
    }

    const int which = o0 >> 9;               // 0=q 1=k 2=v
    const int h = (o0 >> 6) & 7;
    const float sc = (which == 0) ? QSCALE : 1.0f;
    float* dstbase = (which == 0) ? g_Q : (which == 1 ? g_K : g_V);
    #pragma unroll
    for (int r = 0; r < 2; r++) {
        int m = m0 + wm + g + r*8;
        int b = m >> 11, n = m & 2047;
        float* dst = dstbase + ((size_t)(b*NHEAD + h)*SEQ + n)*HD;
        #pragma unroll
        for (int j = 0; j < 8; j++) {
            int c0 = j*8 + t*2;
            float2 bi = *(const float2*)&bias[o0 + c0];
            float2 v;
            v.x = (c[j][r*2 + 0] + bi.x) * sc;
            v.y = (c[j][r*2 + 1] + bi.y) * sc;
            *(float2*)&dst[c0] = v;
        }
    }
}

// ---------------- flash attention (tf32 QK, fp16 PV, register softmax) ----
#define KST 68     // Q/K smem stride (words): bank walk 4/row -> conflict free
#define VST 72     // V fp16 smem stride (halves): 144B rows, LDSM conflict free
__global__ __launch_bounds__(128, 4)
void flash_kernel(const float* __restrict__ mask, float* __restrict__ out) {
    __shared__ unsigned Qs[64*KST];
    __shared__ unsigned Ks[64*KST];
    __shared__ __align__(16) __half Vh[64*VST];
    __shared__ float cpk[64];

    const int b = blockIdx.z, h = blockIdx.y, q0 = blockIdx.x * 64;
    const int tid = threadIdx.x, lane = tid & 31, warp = tid >> 5;
    const int g = lane >> 2, t = lane & 3, wm = warp * 16;

    const size_t base = (size_t)(b*NHEAD + h) * SEQ;
    const float* Qg  = g_Q + (base + q0) * HD;
    const float* Kg  = g_K + base * HD;
    const float* Vg  = g_V + base * HD;
    const float* cpb = g_cp + base;

    // stage Q (tf32) once
    #pragma unroll
    for (int s = 0; s < 8; s++) {
        int slot = tid + s*128;
        int row = slot >> 4, c4 = slot & 15;
        float4 qv = *(const float4*)&Qg[(size_t)row*HD + c4*4];
        uint4 qt = { f2tf(qv.x), f2tf(qv.y), f2tf(qv.z), f2tf(qv.w) };
        *(uint4*)&Qs[row*KST + c4*4] = qt;
    }

    float o[8][4] = {};
    float m_lo = -1e30f, m_hi = -1e30f, l_lo = 0.f, l_hi = 0.f;
    const int r_lo = q0 + wm + g;
    const float* mrow_lo = mask + (size_t)r_lo * SEQ;
    const float* mrow_hi = mask + (size_t)(r_lo + 8) * SEQ;

    for (int kt = 0; kt < SEQ/64; kt++) {
        const int k0 = kt * 64;
        #pragma unroll
        for (int s = 0; s < 8; s++) {
            int slot = tid + s*128;
            int row = slot >> 4, c4 = slot & 15;
            float4 kv = *(const float4*)&Kg[(size_t)(k0+row)*HD + c4*4];
            uint4 ktb = { f2tf(kv.x), f2tf(kv.y), f2tf(kv.z), f2tf(kv.w) };
            *(uint4*)&Ks[row*KST + c4*4] = ktb;
            float4 vv = *(const float4*)&Vg[(size_t)(k0+row)*HD + c4*4];
            uint2 u = { packh2(vv.x, vv.y), packh2(vv.z, vv.w) };
            *(uint2*)&Vh[row*VST + c4*4] = u;
        }
        if (tid < 64) cpk[tid] = cpb[k0 + tid];
        __syncthreads();

        // ---- S = Q·K^T (tf32 mma) ----
        float sreg[8][4] = {};
        #pragma unroll
        for (int kk = 0; kk < 8; kk++) {
            unsigned a[4];
            int ab = (wm + g)*KST + kk*8 + t;
            a[0] = Qs[ab];        a[1] = Qs[ab + 8*KST];
            a[2] = Qs[ab + 4];    a[3] = Qs[ab + 8*KST + 4];
            #pragma unroll
            for (int j = 0; j < 8; j++) {
                int bb = (j*8 + g)*KST + kk*8 + t;
                mma_tf32(sreg[j], a, Ks[bb], Ks[bb + 4]);
            }
        }

        // ---- bias: + mask*LOG2E - cp_k (log2 domain) ----
        #pragma unroll
        for (int j = 0; j < 8; j++) {
            int c0 = j*8 + t*2;
            float2 ml = *(const float2*)&mrow_lo[k0 + c0];
            float2 mh = *(const float2*)&mrow_hi[k0 + c0];
            float2 cp = *(const float2*)&cpk[c0];
            sreg[j][0] += ml.x*LOG2E - cp.x;
            sreg[j][1] += ml.y*LOG2E - cp.y;
            sreg[j][2] += mh.x*LOG2E - cp.x;
            sreg[j][3] += mh.y*LOG2E - cp.y;
        }

        // ---- online softmax (register + quad shfl) ----
        float tl = -1e30f, th = -1e30f;
        #pragma unroll
        for (int j = 0; j < 8; j++) {
            tl = fmaxf(tl, fmaxf(sreg[j][0], sreg[j][1]));
            th = fmaxf(th, fmaxf(sreg[j][2], sreg[j][3]));
        }
        tl = fmaxf(tl, __shfl_xor_sync(0xffffffffu, tl, 1));
        tl = fmaxf(tl, __shfl_xor_sync(0xffffffffu, tl, 2));
        th = fmaxf(th, __shfl_xor_sync(0xffffffffu, th, 1));
        th = fmaxf(th, __shfl_xor_sync(0xffffffffu, th, 2));
        float mnl = fmaxf(m_lo, tl), mnh = fmaxf(m_hi, th);
        float al = exp2f(m_lo - mnl), ah = exp2f(m_hi - mnh);
        m_lo = mnl; m_hi = mnh;
        float sl = 0.f, sh = 0.f;
        #pragma unroll
        for (int j = 0; j < 8; j++) {
            sreg[j][0] = exp2f(sreg[j][0] - mnl);
            sreg[j][1] = exp2f(sreg[j][1] - mnl);
            sreg[j][2] = exp2f(sreg[j][2] - mnh);
            sreg[j][3] = exp2f(sreg[j][3] - mnh);
            sl += sreg[j][0] + sreg[j][1];
            sh += sreg[j][2] + sreg[j][3];
            o[j][0] *= al; o[j][1] *= al; o[j][2] *= ah; o[j][3] *= ah;
        }
        l_lo = l_lo*al + sl;
        l_hi = l_hi*ah + sh;

        // ---- O += P·V  (fp16 mma; S-frag layout == A-frag layout) ----
        #pragma unroll
        for (int jp = 0; jp < 4; jp++) {
            unsigned pa[4];
            pa[0] = packh2(sreg[2*jp][0],   sreg[2*jp][1]);
            pa[1] = packh2(sreg[2*jp][2],   sreg[2*jp][3]);
            pa[2] = packh2(sreg[2*jp+1][0], sreg[2*jp+1][1]);
            pa[3] = packh2(sreg[2*jp+1][2], sreg[2*jp+1][3]);
            #pragma unroll
            for (int np = 0; np < 4; np++) {
                unsigned r0, r1, r2, r3;
                unsigned addr = smem_u32(
                    &Vh[(jp*16 + (lane & 15))*VST + np*16 + ((lane >> 4) << 3)]);
                asm volatile(
                    "ldmatrix.sync.aligned.m8n8.x4.trans.shared.b16 "
                    "{%0,%1,%2,%3}, [%4];"
                    : "=r"(r0), "=r"(r1), "=r"(r2), "=r"(r3) : "r"(addr));
                mma_f16(o[2*np],     pa, r0, r1);
                mma_f16(o[2*np + 1], pa, r2, r3);
            }
        }
        __syncthreads();
    }

    // ---- epilogue ----
    l_lo += __shfl_xor_sync(0xffffffffu, l_lo, 1);
    l_lo += __shfl_xor_sync(0xffffffffu, l_lo, 2);
    l_hi += __shfl_xor_sync(0xffffffffu, l_hi, 1);
    l_hi += __shfl_xor_sync(0xffffffffu, l_hi, 2);
    float il = 1.f / l_lo, ih = 1.f / l_hi;
    #pragma unroll
    for (int j = 0; j < 8; j++) {
        float2 v0 = { o[j][0]*il, o[j][1]*il };
        float2 v1 = { o[j][2]*ih, o[j][3]*ih };
        size_t off = ((size_t)b*SEQ + r_lo)*D_MODEL + h*HD + j*8 + t*2;
        *(float2*)&out[off] = v0;
        *(float2*)&out[off + 8*D_MODEL] = v1;
    }
}

// ---------------- launch ----------------
extern "C" void kernel_launch(void* const* d_in, const int* in_sizes, int n_in,
                              void* d_out, int out_size) {
    const float* x      = (const float*)d_in[0];
    const float* coords = (const float*)d_in[1];
    const float* mask   = (const float*)d_in[2];
    const float* qkv_w  = (const float*)d_in[3];
    const float* qkv_b  = (const float*)d_in[4];
    const float* rw     = (const float*)d_in[5];
    float* out = (float*)d_out;

    coord_proj_kernel<<<(BATCH*NHEAD*SEQ + 255)/256, 256>>>(coords, rw);

    dim3 ggrid(3*D_MODEL/64, BATCH*SEQ/64);
    qkv_gemm_kernel<<<ggrid, 128>>>(x, qkv_w, qkv_b);

    dim3 fgrid(SEQ/64, NHEAD, BATCH);
    flash_kernel<<<fgrid, 128>>>(mask, out);
}

// round 7
// speedup vs baseline: 3.5079x; 1.1011x over previous
#include <cuda_runtime.h>
#include <cuda_fp16.h>

#define D_MODEL 512
#define NHEAD   8
#define HD      64
#define BATCH   2
#define SEQ     2048
#define LOG2E   1.4426950408889634f
#define QSCALE  (0.125f * LOG2E)     // 1/sqrt(64) * log2(e), folded into Q

// ---------------- scratch (fp16 Q/K/V halves L2 traffic) ----------------
__device__ __half g_Q[BATCH*NHEAD*SEQ*HD];   // pre-scaled by QSCALE
__device__ __half g_K[BATCH*NHEAD*SEQ*HD];
__device__ __half g_V[BATCH*NHEAD*SEQ*HD];
__device__ float  g_cp[BATCH*NHEAD*SEQ];     // coord proj ×LOG2E
__device__ __half g_maskh[SEQ*SEQ];          // mask ×LOG2E, fp16

// ---------------- helpers ----------------
static __device__ __forceinline__ unsigned f2tf(float x) {
    unsigned r; asm("cvt.rna.tf32.f32 %0, %1;" : "=r"(r) : "f"(x)); return r;
}
static __device__ __forceinline__ void mma_tf32(float d[4], const unsigned a[4],
                                                unsigned b0, unsigned b1) {
    asm volatile("mma.sync.aligned.m16n8k8.row.col.f32.tf32.tf32.f32 "
                 "{%0,%1,%2,%3},{%4,%5,%6,%7},{%8,%9},{%0,%1,%2,%3};"
                 : "+f"(d[0]), "+f"(d[1]), "+f"(d[2]), "+f"(d[3])
                 : "r"(a[0]), "r"(a[1]), "r"(a[2]), "r"(a[3]), "r"(b0), "r"(b1));
}
static __device__ __forceinline__ void mma_f16(float d[4], const unsigned a[4],
                                               unsigned b0, unsigned b1) {
    asm volatile("mma.sync.aligned.m16n8k16.row.col.f32.f16.f16.f32 "
                 "{%0,%1,%2,%3},{%4,%5,%6,%7},{%8,%9},{%0,%1,%2,%3};"
                 : "+f"(d[0]), "+f"(d[1]), "+f"(d[2]), "+f"(d[3])
                 : "r"(a[0]), "r"(a[1]), "r"(a[2]), "r"(a[3]), "r"(b0), "r"(b1));
}
static __device__ __forceinline__ unsigned packh2(float a, float b) {
    __half2 h = __floats2half2_rn(a, b);
    return *reinterpret_cast<unsigned*>(&h);
}
static __device__ __forceinline__ unsigned smem_u32(const void* p) {
    return (unsigned)__cvta_generic_to_shared(p);
}
static __device__ __forceinline__ void ldsm_x4(unsigned& r0, unsigned& r1,
                                               unsigned& r2, unsigned& r3,
                                               unsigned addr) {
    asm volatile("ldmatrix.sync.aligned.m8n8.x4.shared.b16 {%0,%1,%2,%3}, [%4];"
                 : "=r"(r0), "=r"(r1), "=r"(r2), "=r"(r3) : "r"(addr));
}
static __device__ __forceinline__ void ldsm_x4t(unsigned& r0, unsigned& r1,
                                                unsigned& r2, unsigned& r3,
                                                unsigned addr) {
    asm volatile("ldmatrix.sync.aligned.m8n8.x4.trans.shared.b16 {%0,%1,%2,%3}, [%4];"
                 : "=r"(r0), "=r"(r1), "=r"(r2), "=r"(r3) : "r"(addr));
}

// ---------------- coord projection (×LOG2E) ----------------
__global__ void coord_proj_kernel(const float* __restrict__ coords,
                                  const float* __restrict__ rw) {
    int idx = blockIdx.x * blockDim.x + threadIdx.x;
    if (idx >= BATCH*NHEAD*SEQ) return;
    int n = idx & (SEQ - 1);
    int h = (idx >> 11) & 7;
    int b = idx >> 14;
    const float* c = coords + (b*SEQ + n)*3;
    const float* w = rw + h*3;
    g_cp[idx] = (c[0]*w[0] + c[1]*w[1] + c[2]*w[2]) * LOG2E;
}

// ---------------- mask prep: ×LOG2E, fp32 -> fp16 ----------------
__global__ void mask_prep_kernel(const float* __restrict__ mask) {
    int i = blockIdx.x * blockDim.x + threadIdx.x;   // one float4 each
    float4 m = ((const float4*)mask)[i];
    __half2* dst = (__half2*)g_maskh;
    dst[i*2]     = __floats2half2_rn(m.x*LOG2E, m.y*LOG2E);
    dst[i*2 + 1] = __floats2half2_rn(m.z*LOG2E, m.w*LOG2E);
}

// ---------------- QKV GEMM (tf32 mma, pair-permuted smem, fp16 out) ------
// Permutation within each 8-col k-chunk: col c -> (c&3)*2 + (c>>2), so a
// thread's (t, t+4) fragment pair is one LDS.64.
#define GS 36
__global__ __launch_bounds__(128)
void qkv_gemm_kernel(const float* __restrict__ x,
                     const float* __restrict__ w,
                     const float* __restrict__ bias) {
    __shared__ unsigned Xs[64*GS];
    __shared__ unsigned Ws[64*GS];
    const int m0 = blockIdx.y * 64, o0 = blockIdx.x * 64;
    const int tid = threadIdx.x, lane = tid & 31, warp = tid >> 5;
    const int g = lane >> 2, t = lane & 3, wm = warp * 16;

    float c[8][4] = {};

    for (int k0 = 0; k0 < D_MODEL; k0 += 32) {
        #pragma unroll
        for (int s = 0; s < 4; s++) {
            int slot = tid + s*128;               // 0..511
            int row = slot >> 3, c4 = slot & 7;   // 64 rows x 8 float4
            float4 xv = *(const float4*)&x[(size_t)(m0+row)*D_MODEL + k0 + c4*4];
            float4 wv = *(const float4*)&w[(size_t)(o0+row)*D_MODEL + k0 + c4*4];
            int off = row*GS + (c4 >> 1)*8 + (c4 & 1);   // permuted base
            Xs[off+0]=f2tf(xv.x); Xs[off+2]=f2tf(xv.y);
            Xs[off+4]=f2tf(xv.z); Xs[off+6]=f2tf(xv.w);
            Ws[off+0]=f2tf(wv.x); Ws[off+2]=f2tf(wv.y);
            Ws[off+4]=f2tf(wv.z); Ws[off+6]=f2tf(wv.w);
        }
        __syncthreads();
        #pragma unroll
        for (int kk = 0; kk < 4; kk++) {
            unsigned a[4];
            uint2 a02 = *(uint2*)&Xs[(wm + g)*GS     + kk*8 + t*2];
            uint2 a13 = *(uint2*)&Xs[(wm + g + 8)*GS + kk*8 + t*2];
            a[0]=a02.x; a[2]=a02.y; a[1]=a13.x; a[3]=a13.y;
            #pragma unroll
            for (int j = 0; j < 8; j++) {
                uint2 bb = *(uint2*)&Ws[(j*8 + g)*GS + kk*8 + t*2];
                mma_tf32(c[j], a, bb.x, bb.y);
            }
        }
        __syncthreads();
    }

    const int which = o0 >> 9;               // 0=q 1=k 2=v
    const int h = (o0 >> 6) & 7;
    const float sc = (which == 0) ? QSCALE : 1.0f;
    __half* dstbase = (which == 0) ? g_Q : (which == 1 ? g_K : g_V);
    #pragma unroll
    for (int r = 0; r < 2; r++) {
        int m = m0 + wm + g + r*8;
        int b = m >> 11, n = m & 2047;
        __half* dst = dstbase + ((size_t)(b*NHEAD + h)*SEQ + n)*HD;
        #pragma unroll
        for (int j = 0; j < 8; j++) {
            int c0 = j*8 + t*2;
            float2 bi = *(const float2*)&bias[o0 + c0];
            *(__half2*)&dst[c0] = __floats2half2_rn(
                (c[j][r*2 + 0] + bi.x) * sc,
                (c[j][r*2 + 1] + bi.y) * sc);
        }
    }
}

// ---------------- flash attention (fp16 mma everywhere) -------------------
// 128-query tile, 256 threads (8 warps x 16 rows), 64-key tiles.
// Smem fp16 stride 72 halves (144B rows) -> conflict-free ldmatrix.
#define ST 72
__global__ __launch_bounds__(256, 2)
void flash_kernel(float* __restrict__ out) {
    __shared__ __align__(16) __half Qh[128*ST];
    __shared__ __align__(16) __half Kh[64*ST];
    __shared__ __align__(16) __half Vh[64*ST];
    __shared__ float cpk[64];

    const int b = blockIdx.z, h = blockIdx.y, q0 = blockIdx.x * 128;
    const int tid = threadIdx.x, lane = tid & 31, warp = tid >> 5;
    const int g = lane >> 2, t = lane & 3, wm = warp * 16;
    const int lrow = lane & 15, lcol = (lane >> 4) << 3;

    const size_t base = (size_t)(b*NHEAD + h) * SEQ;
    const __half* Qg  = g_Q + (base + q0) * HD;
    const __half* Kg  = g_K + base * HD;
    const __half* Vg  = g_V + base * HD;
    const float*  cpb = g_cp + base;

    // stage Q once (fp16, pre-scaled): 128 rows x 8 uint4
    #pragma unroll
    for (int s = 0; s < 4; s++) {
        int slot = tid + s*256;
        int row = slot >> 3, c8 = slot & 7;
        *(uint4*)&Qh[row*ST + c8*8] = *(const uint4*)&Qg[(size_t)row*HD + c8*8];
    }

    float o[8][4] = {};
    float m_lo = -1e30f, m_hi = -1e30f, l_lo = 0.f, l_hi = 0.f;
    const int r_lo = q0 + wm + g;
    const __half* mrow_lo = g_maskh + (size_t)r_lo * SEQ;
    const __half* mrow_hi = g_maskh + (size_t)(r_lo + 8) * SEQ;

    for (int kt = 0; kt < SEQ/64; kt++) {
        const int k0 = kt * 64;
        #pragma unroll
        for (int s = 0; s < 2; s++) {
            int slot = tid + s*256;
            int row = slot >> 3, c8 = slot & 7;
            *(uint4*)&Kh[row*ST + c8*8] = *(const uint4*)&Kg[(size_t)(k0+row)*HD + c8*8];
            *(uint4*)&Vh[row*ST + c8*8] = *(const uint4*)&Vg[(size_t)(k0+row)*HD + c8*8];
        }
        if (tid < 64) cpk[tid] = cpb[k0 + tid];
        __syncthreads();

        // ---- S = Q·K^T  (fp16 m16n8k16, ldmatrix operands) ----
        float sreg[8][4] = {};
        #pragma unroll
        for (int kk = 0; kk < 4; kk++) {
            unsigned qa[4];
            ldsm_x4(qa[0], qa[1], qa[2], qa[3],
                    smem_u32(&Qh[(wm + lrow)*ST + kk*16 + lcol]));
            #pragma unroll
            for (int j = 0; j < 4; j++) {
                unsigned r0, r1, r2, r3;
                ldsm_x4(r0, r1, r2, r3,
                        smem_u32(&Kh[(j*16 + lrow)*ST + kk*16 + lcol]));
                mma_f16(sreg[2*j],     qa, r0, r2);
                mma_f16(sreg[2*j + 1], qa, r1, r3);
            }
        }

        // ---- bias: + mask (already ×LOG2E, fp16) - cp_k ----
        #pragma unroll
        for (int j = 0; j < 8; j++) {
            int c0 = j*8 + t*2;
            float2 ml = __half22float2(*(const __half2*)&mrow_lo[k0 + c0]);
            float2 mh = __half22float2(*(const __half2*)&mrow_hi[k0 + c0]);
            float2 cp = *(const float2*)&cpk[c0];
            sreg[j][0] += ml.x - cp.x;
            sreg[j][1] += ml.y - cp.y;
            sreg[j][2] += mh.x - cp.x;
            sreg[j][3] += mh.y - cp.y;
        }

        // ---- online softmax (registers + quad shfl) ----
        float tl = -1e30f, th = -1e30f;
        #pragma unroll
        for (int j = 0; j < 8; j++) {
            tl = fmaxf(tl, fmaxf(sreg[j][0], sreg[j][1]));
            th = fmaxf(th, fmaxf(sreg[j][2], sreg[j][3]));
        }
        tl = fmaxf(tl, __shfl_xor_sync(0xffffffffu, tl, 1));
        tl = fmaxf(tl, __shfl_xor_sync(0xffffffffu, tl, 2));
        th = fmaxf(th, __shfl_xor_sync(0xffffffffu, th, 1));
        th = fmaxf(th, __shfl_xor_sync(0xffffffffu, th, 2));
        float mnl = fmaxf(m_lo, tl), mnh = fmaxf(m_hi, th);
        float al = exp2f(m_lo - mnl), ah = exp2f(m_hi - mnh);
        m_lo = mnl; m_hi = mnh;
        float sl = 0.f, sh = 0.f;
        #pragma unroll
        for (int j = 0; j < 8; j++) {
            sreg[j][0] = exp2f(sreg[j][0] - mnl);
            sreg[j][1] = exp2f(sreg[j][1] - mnl);
            sreg[j][2] = exp2f(sreg[j][2] - mnh);
            sreg[j][3] = exp2f(sreg[j][3] - mnh);
            sl += sreg[j][0] + sreg[j][1];
            sh += sreg[j][2] + sreg[j][3];
            o[j][0] *= al; o[j][1] *= al; o[j][2] *= ah; o[j][3] *= ah;
        }
        l_lo = l_lo*al + sl;
        l_hi = l_hi*ah + sh;

        // ---- O += P·V  (fp16 mma; S-frag layout == A-frag layout) ----
        #pragma unroll
        for (int jp = 0; jp < 4; jp++) {
            unsigned pa[4];
            pa[0] = packh2(sreg[2*jp][0],   sreg[2*jp][1]);
            pa[1] = packh2(sreg[2*jp][2],   sreg[2*jp][3]);
            pa[2] = packh2(sreg[2*jp+1][0], sreg[2*jp+1][1]);
            pa[3] = packh2(sreg[2*jp+1][2], sreg[2*jp+1][3]);
            #pragma unroll
            for (int np = 0; np < 4; np++) {
                unsigned r0, r1, r2, r3;
                ldsm_x4t(r0, r1, r2, r3,
                         smem_u32(&Vh[(jp*16 + lrow)*ST + np*16 + lcol]));
                mma_f16(o[2*np],     pa, r0, r1);
                mma_f16(o[2*np + 1], pa, r2, r3);
            }
        }
        __syncthreads();   // Kh/Vh reuse
    }

    // ---- epilogue ----
    l_lo += __shfl_xor_sync(0xffffffffu, l_lo, 1);
    l_lo += __shfl_xor_sync(0xffffffffu, l_lo, 2);
    l_hi += __shfl_xor_sync(0xffffffffu, l_hi, 1);
    l_hi += __shfl_xor_sync(0xffffffffu, l_hi, 2);
    float il = 1.f / l_lo, ih = 1.f / l_hi;
    #pragma unroll
    for (int j = 0; j < 8; j++) {
        float2 v0 = { o[j][0]*il, o[j][1]*il };
        float2 v1 = { o[j][2]*ih, o[j][3]*ih };
        size_t off = ((size_t)b*SEQ + r_lo)*D_MODEL + h*HD + j*8 + t*2;
        *(float2*)&out[off] = v0;
        *(float2*)&out[off + 8*D_MODEL] = v1;
    }
}

// ---------------- launch ----------------
extern "C" void kernel_launch(void* const* d_in, const int* in_sizes, int n_in,
                              void* d_out, int out_size) {
    const float* x      = (const float*)d_in[0];
    const float* coords = (const float*)d_in[1];
    const float* mask   = (const float*)d_in[2];
    const float* qkv_w  = (const float*)d_in[3];
    const float* qkv_b  = (const float*)d_in[4];
    const float* rw     = (const float*)d_in[5];
    float* out = (float*)d_out;

    coord_proj_kernel<<<(BATCH*NHEAD*SEQ + 255)/256, 256>>>(coords, rw);
    mask_prep_kernel<<<(SEQ*SEQ/4 + 255)/256, 256>>>(mask);

    dim3 ggrid(3*D_MODEL/64, BATCH*SEQ/64);
    qkv_gemm_kernel<<<ggrid, 128>>>(x, qkv_w, qkv_b);

    dim3 fgrid(SEQ/128, NHEAD, BATCH);
    flash_kernel<<<fgrid, 256>>>(out);
}

// round 8
// speedup vs baseline: 5.1384x; 1.4648x over previous
#include <cuda_runtime.h>
#include <cuda_fp16.h>

#define D_MODEL 512
#define NHEAD   8
#define HD      64
#define BATCH   2
#define SEQ     2048
#define LOG2E   1.4426950408889634f
#define QSCALE  (0.125f * LOG2E)     // 1/sqrt(64) * log2(e), folded into Q

// ---------------- scratch ----------------
__device__ __half g_Q[BATCH*NHEAD*SEQ*HD];   // pre-scaled by QSCALE
__device__ __half g_K[BATCH*NHEAD*SEQ*HD];
__device__ __half g_V[BATCH*NHEAD*SEQ*HD];
__device__ float  g_cp[BATCH*NHEAD*SEQ];     // coord proj ×LOG2E
__device__ __half g_maskh[SEQ*SEQ];          // mask ×LOG2E, fp16
__device__ __half g_xh[BATCH*SEQ*D_MODEL];   // x in fp16
__device__ __half g_wh[3*D_MODEL*D_MODEL];   // qkv_w in fp16

// ---------------- helpers ----------------
static __device__ __forceinline__ void mma_f16(float d[4], const unsigned a[4],
                                               unsigned b0, unsigned b1) {
    asm volatile("mma.sync.aligned.m16n8k16.row.col.f32.f16.f16.f32 "
                 "{%0,%1,%2,%3},{%4,%5,%6,%7},{%8,%9},{%0,%1,%2,%3};"
                 : "+f"(d[0]), "+f"(d[1]), "+f"(d[2]), "+f"(d[3])
                 : "r"(a[0]), "r"(a[1]), "r"(a[2]), "r"(a[3]), "r"(b0), "r"(b1));
}
static __device__ __forceinline__ unsigned packh2(float a, float b) {
    __half2 h = __floats2half2_rn(a, b);
    return *reinterpret_cast<unsigned*>(&h);
}
static __device__ __forceinline__ unsigned smem_u32(const void* p) {
    return (unsigned)__cvta_generic_to_shared(p);
}
static __device__ __forceinline__ void ldsm_x4(unsigned& r0, unsigned& r1,
                                               unsigned& r2, unsigned& r3,
                                               unsigned addr) {
    asm volatile("ldmatrix.sync.aligned.m8n8.x4.shared.b16 {%0,%1,%2,%3}, [%4];"
                 : "=r"(r0), "=r"(r1), "=r"(r2), "=r"(r3) : "r"(addr));
}
static __device__ __forceinline__ void ldsm_x4t(unsigned& r0, unsigned& r1,
                                                unsigned& r2, unsigned& r3,
                                                unsigned addr) {
    asm volatile("ldmatrix.sync.aligned.m8n8.x4.trans.shared.b16 {%0,%1,%2,%3}, [%4];"
                 : "=r"(r0), "=r"(r1), "=r"(r2), "=r"(r3) : "r"(addr));
}
static __device__ __forceinline__ void cp16(unsigned dst, const void* src) {
    asm volatile("cp.async.cg.shared.global [%0], [%1], 16;"
                 :: "r"(dst), "l"(src));
}
#define CP_COMMIT() asm volatile("cp.async.commit_group;")
#define CP_WAIT(n)  asm volatile("cp.async.wait_group %0;" :: "n"(n))

// ---------------- prep kernels ----------------
__global__ void coord_proj_kernel(const float* __restrict__ coords,
                                  const float* __restrict__ rw) {
    int idx = blockIdx.x * blockDim.x + threadIdx.x;
    if (idx >= BATCH*NHEAD*SEQ) return;
    int n = idx & (SEQ - 1);
    int h = (idx >> 11) & 7;
    int b = idx >> 14;
    const float* c = coords + (b*SEQ + n)*3;
    const float* w = rw + h*3;
    g_cp[idx] = (c[0]*w[0] + c[1]*w[1] + c[2]*w[2]) * LOG2E;
}
__global__ void mask_prep_kernel(const float* __restrict__ mask) {
    int i = blockIdx.x * blockDim.x + threadIdx.x;
    float4 m = ((const float4*)mask)[i];
    __half2* dst = (__half2*)g_maskh;
    dst[i*2]     = __floats2half2_rn(m.x*LOG2E, m.y*LOG2E);
    dst[i*2 + 1] = __floats2half2_rn(m.z*LOG2E, m.w*LOG2E);
}
__global__ void cvt_h_kernel(const float* __restrict__ src, __half* dst, int n4) {
    int i = blockIdx.x * blockDim.x + threadIdx.x;
    if (i >= n4) return;
    float4 v = ((const float4*)src)[i];
    __half2* d = (__half2*)dst;
    d[i*2]     = __floats2half2_rn(v.x, v.y);
    d[i*2 + 1] = __floats2half2_rn(v.z, v.w);
}

// ---------------- QKV GEMM: fp16 mma, cp.async double buffer ------------
// 128x64 tile, K-chunk 64, 256 threads (8 warps x 16 rows).
#define GST 72
#define G_SMEM ((2*128*GST + 2*64*GST) * 2)     // 55296 bytes

__global__ __launch_bounds__(256)
void qkv_gemm_kernel(const float* __restrict__ bias) {
    extern __shared__ __align__(16) char smraw[];
    __half* Xs = (__half*)smraw;                 // 2 stages x 128*GST
    __half* Ws = (__half*)smraw + 2*128*GST;     // 2 stages x 64*GST
    const int m0 = blockIdx.y * 128, o0 = blockIdx.x * 64;
    const int tid = threadIdx.x, lane = tid & 31, warp = tid >> 5;
    const int g = lane >> 2, t = lane & 3, wm = warp * 16;
    const int lrow = lane & 15, lcol = (lane >> 4) << 3;

    const __half* xg = g_xh + (size_t)m0 * D_MODEL;
    const __half* wg = g_wh + (size_t)o0 * D_MODEL;

    auto issue = [&](int ch, int stg) {
        int kb = ch * 64;
        #pragma unroll
        for (int s = 0; s < 4; s++) {
            int slot = tid + s*256;                 // X: 128 rows x 8
            int row = slot >> 3, c8 = slot & 7;
            cp16(smem_u32(&Xs[stg*128*GST + row*GST + c8*8]),
                 xg + (size_t)row*D_MODEL + kb + c8*8);
        }
        #pragma unroll
        for (int s = 0; s < 2; s++) {
            int slot = tid + s*256;                 // W: 64 rows x 8
            int row = slot >> 3, c8 = slot & 7;
            cp16(smem_u32(&Ws[stg*64*GST + row*GST + c8*8]),
                 wg + (size_t)row*D_MODEL + kb + c8*8);
        }
    };

    float c[8][4] = {};
    issue(0, 0); CP_COMMIT();

    for (int ch = 0; ch < 8; ch++) {
        int cb = ch & 1;
        if (ch < 7) { issue(ch + 1, cb ^ 1); CP_COMMIT(); CP_WAIT(1); }
        else        { CP_WAIT(0); }
        __syncthreads();
        const __half* X = Xs + cb*128*GST;
        const __half* W = Ws + cb*64*GST;
        #pragma unroll
        for (int kk = 0; kk < 4; kk++) {
            unsigned a[4];
            ldsm_x4(a[0], a[1], a[2], a[3],
                    smem_u32(&X[(wm + lrow)*GST + kk*16 + lcol]));
            #pragma unroll
            for (int j = 0; j < 4; j++) {
                unsigned r0, r1, r2, r3;
                ldsm_x4(r0, r1, r2, r3,
                        smem_u32(&W[(j*16 + lrow)*GST + kk*16 + lcol]));
                mma_f16(c[2*j],     a, r0, r2);
                mma_f16(c[2*j + 1], a, r1, r3);
            }
        }
        __syncthreads();
    }

    const int which = o0 >> 9;               // 0=q 1=k 2=v
    const int h = (o0 >> 6) & 7;
    const float sc = (which == 0) ? QSCALE : 1.0f;
    __half* dstbase = (which == 0) ? g_Q : (which == 1 ? g_K : g_V);
    #pragma unroll
    for (int r = 0; r < 2; r++) {
        int m = m0 + wm + g + r*8;
        int b = m >> 11, n = m & 2047;
        __half* dst = dstbase + ((size_t)(b*NHEAD + h)*SEQ + n)*HD;
        #pragma unroll
        for (int j = 0; j < 8; j++) {
            int c0 = j*8 + t*2;
            float2 bi = *(const float2*)&bias[o0 + c0];
            *(__half2*)&dst[c0] = __floats2half2_rn(
                (c[j][r*2 + 0] + bi.x) * sc,
                (c[j][r*2 + 1] + bi.y) * sc);
        }
    }
}

// ---------------- flash attention: cp.async pipeline, ones-column l ------
#define ST 72
#define F_SMEM ((128*ST + 2*64*ST + 2*64*ST)*2 + 2*64*4)   // 55808 bytes
#define ONE2 0x3C003C00u

__global__ __launch_bounds__(256, 2)
void flash_kernel(float* __restrict__ out) {
    extern __shared__ __align__(16) char smraw[];
    __half* Qh  = (__half*)smraw;                 // 128*ST
    __half* Kh  = Qh + 128*ST;                    // 2 stages x 64*ST
    __half* Vh  = Kh + 2*64*ST;                   // 2 stages x 64*ST
    float*  cpk = (float*)(Vh + 2*64*ST);         // 2 stages x 64

    const int b = blockIdx.z, h = blockIdx.y, q0 = blockIdx.x * 128;
    const int tid = threadIdx.x, lane = tid & 31, warp = tid >> 5;
    const int g = lane >> 2, t = lane & 3, wm = warp * 16;
    const int lrow = lane & 15, lcol = (lane >> 4) << 3;

    const size_t base = (size_t)(b*NHEAD + h) * SEQ;
    const __half* Qg  = g_Q + (base + q0) * HD;
    const __half* Kg  = g_K + base * HD;
    const __half* Vg  = g_V + base * HD;
    const float*  cpb = g_cp + base;

    auto issue_kv = [&](int kt, int stg) {
        int k0 = kt * 64;
        #pragma unroll
        for (int s = 0; s < 2; s++) {
            int slot = tid + s*256;                 // 64 rows x 8
            int row = slot >> 3, c8 = slot & 7;
            cp16(smem_u32(&Kh[stg*64*ST + row*ST + c8*8]),
                 Kg + (size_t)(k0+row)*HD + c8*8);
            cp16(smem_u32(&Vh[stg*64*ST + row*ST + c8*8]),
                 Vg + (size_t)(k0+row)*HD + c8*8);
        }
        if (tid < 16) cp16(smem_u32(&cpk[stg*64 + tid*4]), cpb + k0 + tid*4);
    };

    // stage Q + first KV tile (group 0)
    #pragma unroll
    for (int s = 0; s < 4; s++) {
        int slot = tid + s*256;
        int row = slot >> 3, c8 = slot & 7;
        cp16(smem_u32(&Qh[row*ST + c8*8]), Qg + (size_t)row*HD + c8*8);
    }
    issue_kv(0, 0); CP_COMMIT();

    float o[8][4] = {};
    float l_acc[4] = {};
    float m_lo = -1e30f, m_hi = -1e30f;
    const int r_lo = q0 + wm + g;
    const __half* mrow_lo = g_maskh + (size_t)r_lo * SEQ;
    const __half* mrow_hi = g_maskh + (size_t)(r_lo + 8) * SEQ;

    for (int kt = 0; kt < SEQ/64; kt++) {
        const int k0 = kt * 64;
        const int cb = kt & 1;
        if (kt < SEQ/64 - 1) { issue_kv(kt + 1, cb ^ 1); CP_COMMIT(); CP_WAIT(1); }
        else                 { CP_WAIT(0); }
        __syncthreads();

        // prefetch mask tile into registers (L2 latency hidden behind mma)
        unsigned mlv[8], mhv[8];
        #pragma unroll
        for (int j = 0; j < 8; j++) {
            mlv[j] = *(const unsigned*)&mrow_lo[k0 + j*8 + t*2];
            mhv[j] = *(const unsigned*)&mrow_hi[k0 + j*8 + t*2];
        }

        const __half* K = Kh + cb*64*ST;
        const __half* V = Vh + cb*64*ST;
        const float*  cp = cpk + cb*64;

        // ---- S = Q·K^T ----
        float sreg[8][4] = {};
        #pragma unroll
        for (int kk = 0; kk < 4; kk++) {
            unsigned qa[4];
            ldsm_x4(qa[0], qa[1], qa[2], qa[3],
                    smem_u32(&Qh[(wm + lrow)*ST + kk*16 + lcol]));
            #pragma unroll
            for (int j = 0; j < 4; j++) {
                unsigned r0, r1, r2, r3;
                ldsm_x4(r0, r1, r2, r3,
                        smem_u32(&K[(j*16 + lrow)*ST + kk*16 + lcol]));
                mma_f16(sreg[2*j],     qa, r0, r2);
                mma_f16(sreg[2*j + 1], qa, r1, r3);
            }
        }

        // ---- bias: + mask(×LOG2E fp16) - cp_k ----
        #pragma unroll
        for (int j = 0; j < 8; j++) {
            int c0 = j*8 + t*2;
            float2 ml = __half22float2(*(const __half2*)&mlv[j]);
            float2 mh = __half22float2(*(const __half2*)&mhv[j]);
            float2 cpv = *(const float2*)&cp[c0];
            sreg[j][0] += ml.x - cpv.x;
            sreg[j][1] += ml.y - cpv.y;
            sreg[j][2] += mh.x - cpv.x;
            sreg[j][3] += mh.y - cpv.y;
        }

        // ---- online softmax (registers + quad shfl) ----
        float tl = -1e30f, th = -1e30f;
        #pragma unroll
        for (int j = 0; j < 8; j++) {
            tl = fmaxf(tl, fmaxf(sreg[j][0], sreg[j][1]));
            th = fmaxf(th, fmaxf(sreg[j][2], sreg[j][3]));
        }
        tl = fmaxf(tl, __shfl_xor_sync(0xffffffffu, tl, 1));
        tl = fmaxf(tl, __shfl_xor_sync(0xffffffffu, tl, 2));
        th = fmaxf(th, __shfl_xor_sync(0xffffffffu, th, 1));
        th = fmaxf(th, __shfl_xor_sync(0xffffffffu, th, 2));
        float mnl = fmaxf(m_lo, tl), mnh = fmaxf(m_hi, th);
        float al = exp2f(m_lo - mnl), ah = exp2f(m_hi - mnh);
        m_lo = mnl; m_hi = mnh;
        #pragma unroll
        for (int j = 0; j < 8; j++) {
            sreg[j][0] = exp2f(sreg[j][0] - mnl);
            sreg[j][1] = exp2f(sreg[j][1] - mnl);
            sreg[j][2] = exp2f(sreg[j][2] - mnh);
            sreg[j][3] = exp2f(sreg[j][3] - mnh);
            o[j][0] *= al; o[j][1] *= al; o[j][2] *= ah; o[j][3] *= ah;
        }
        l_acc[0] *= al; l_acc[1] *= al; l_acc[2] *= ah; l_acc[3] *= ah;

        // ---- O += P·V ; l += P·1 (ones-column mma, exact) ----
        #pragma unroll
        for (int jp = 0; jp < 4; jp++) {
            unsigned pa[4];
            pa[0] = packh2(sreg[2*jp][0],   sreg[2*jp][1]);
            pa[1] = packh2(sreg[2*jp][2],   sreg[2*jp][3]);
            pa[2] = packh2(sreg[2*jp+1][0], sreg[2*jp+1][1]);
            pa[3] = packh2(sreg[2*jp+1][2], sreg[2*jp+1][3]);
            #pragma unroll
            for (int np = 0; np < 4; np++) {
                unsigned r0, r1, r2, r3;
                ldsm_x4t(r0, r1, r2, r3,
                         smem_u32(&V[(jp*16 + lrow)*ST + np*16 + lcol]));
                mma_f16(o[2*np],     pa, r0, r1);
                mma_f16(o[2*np + 1], pa, r2, r3);
            }
            mma_f16(l_acc, pa, ONE2, ONE2);
        }
        __syncthreads();
    }

    // ---- epilogue (l_acc holds full row sums; no shuffles needed) ----
    float il = 1.f / l_acc[0], ih = 1.f / l_acc[2];
    #pragma unroll
    for (int j = 0; j < 8; j++) {
        float2 v0 = { o[j][0]*il, o[j][1]*il };
        float2 v1 = { o[j][2]*ih, o[j][3]*ih };
        size_t off = ((size_t)b*SEQ + r_lo)*D_MODEL + h*HD + j*8 + t*2;
        *(float2*)&out[off] = v0;
        *(float2*)&out[off + 8*D_MODEL] = v1;
    }
}

// ---------------- launch ----------------
extern "C" void kernel_launch(void* const* d_in, const int* in_sizes, int n_in,
                              void* d_out, int out_size) {
    const float* x      = (const float*)d_in[0];
    const float* coords = (const float*)d_in[1];
    const float* mask   = (const float*)d_in[2];
    const float* qkv_w  = (const float*)d_in[3];
    const float* qkv_b  = (const float*)d_in[4];
    const float* rw     = (const float*)d_in[5];
    float* out = (float*)d_out;

    coord_proj_kernel<<<(BATCH*NHEAD*SEQ + 255)/256, 256>>>(coords, rw);
    mask_prep_kernel<<<(SEQ*SEQ/4 + 255)/256, 256>>>(mask);

    __half* xh; cudaGetSymbolAddress((void**)&xh, g_xh);
    __half* wh; cudaGetSymbolAddress((void**)&wh, g_wh);
    int nx4 = BATCH*SEQ*D_MODEL/4, nw4 = 3*D_MODEL*D_MODEL/4;
    cvt_h_kernel<<<(nx4 + 255)/256, 256>>>(x, xh, nx4);
    cvt_h_kernel<<<(nw4 + 255)/256, 256>>>(qkv_w, wh, nw4);

    cudaFuncSetAttribute(qkv_gemm_kernel,
                         cudaFuncAttributeMaxDynamicSharedMemorySize, G_SMEM);
    dim3 ggrid(3*D_MODEL/64, BATCH*SEQ/128);
    qkv_gemm_kernel<<<ggrid, 256, G_SMEM>>>(qkv_b);

    cudaFuncSetAttribute(flash_kernel,
                         cudaFuncAttributeMaxDynamicSharedMemorySize, F_SMEM);
    dim3 fgrid(SEQ/128, NHEAD, BATCH);
    flash_kernel<<<fgrid, 256, F_SMEM>>>(out);
}